// round 13
// baseline (speedup 1.0000x reference)
#include <cuda_runtime.h>
#include <cuda_fp16.h>
#include <cstdint>

#define THREADS 1024
#define GTILES  8
#define GROUPS  128                 // row-groups of 2048 rows
#define NBLOCKS (6 * GROUPS)        // 768
#define XTILE_BYTES 14464           // one 64-row fp16 X tile, grouped-224 layout

// ---------------- smem layout (bytes), ONE CTA per SM ----------------
// 4 quarters (256 thr each), each with its own X / H1 / H2; weights shared.
#define ACT_STRIDE 39040    // per-quarter: X 14464 + H1 16384 + H2 8192
#define X_OFF   0           // 14464 (grouped-224)
#define H1_OFF  14464       // 16384 (64 x 256B XOR swz)
#define H2_OFF  30848       // 8192  (64 x 128B XOR swz)
#define W1_HI   156160      // 28928 (128 rows grouped-224)
#define W2_OFF  185088      // 16384 (64 x 256B swz)
#define W3_OFF  201472      // 4096  (32 x 128B swz)
#define B1H     205568      // half2 [64]
#define B2H     205824      // half2 [32]
#define B3S     205952      // fp32 [32]
#define W4S     206080      // fp32 [32]
#define B4S     206208      // fp32 [1]
#define FLAG    206212      // int
#define SMEM_BYTES 206336

__device__ int g_cnt[GROUPS];                       // zero-init; restored each launch
__device__ __align__(16) char g_xf16[4096 * XTILE_BYTES];   // prepass fp16 X tiles

__device__ __forceinline__ uint32_t smem_u32(const void* p) {
    uint32_t a;
    asm("{ .reg .u64 t; cvta.to.shared.u64 t, %1; cvt.u32.u64 %0, t; }"
        : "=r"(a) : "l"(p));
    return a;
}

__host__ __device__ __forceinline__ uint32_t rowoff224(int r) {
    return (uint32_t)((r >> 3) * 1808 + (r & 7) * 224 + ((r & 4) << 2));
}

#define LDSM4(R0, R1, R2, R3, ADDR)                                        \
    asm volatile("ldmatrix.sync.aligned.m8n8.x4.shared.b16 {%0,%1,%2,%3},[%4];" \
                 : "=r"(R0), "=r"(R1), "=r"(R2), "=r"(R3) : "r"(ADDR))

#define STS32(ADDR, V) \
    asm volatile("st.shared.b32 [%0], %1;" :: "r"(ADDR), "r"(V) : "memory")

#define BARQ(id) asm volatile("bar.sync %0, 256;" :: "r"(id) : "memory")
#define CP_WAIT() asm volatile("cp.async.wait_group 0;" ::: "memory")

__device__ __forceinline__ void mma16816(float c[4], const uint32_t a[4],
                                         uint32_t b0, uint32_t b1) {
    asm volatile(
        "mma.sync.aligned.m16n8k16.row.col.f32.f16.f16.f32 "
        "{%0,%1,%2,%3},{%4,%5,%6,%7},{%8,%9},{%0,%1,%2,%3};\n"
        : "+f"(c[0]), "+f"(c[1]), "+f"(c[2]), "+f"(c[3])
        : "r"(a[0]), "r"(a[1]), "r"(a[2]), "r"(a[3]), "r"(b0), "r"(b1));
}

// fp32 silu via MUFU tanh
__device__ __forceinline__ float silu_f(float x) {
    float t;
    asm("tanh.approx.f32 %0, %1;" : "=f"(t) : "f"(0.5f * x));
    return x * fmaf(0.5f, t, 0.5f);
}

// packed half2 silu via tanh.approx.f16x2
__device__ __forceinline__ __half2 silu_h2(__half2 x) {
    const __half2 h05 = __floats2half2_rn(0.5f, 0.5f);
    __half2 t = __hmul2(x, h05);
    uint32_t th;
    asm("tanh.approx.f16x2 %0, %1;" : "=r"(th) : "r"(*(uint32_t*)&t));
    __half2 s = __hfma2(*(__half2*)&th, h05, h05);
    return __hmul2(x, s);
}

// ---------------- linear mainloop (layer 1: grouped-224 A and B) ----------------
template <int MT, int NTP, int KT>
__device__ __forceinline__ void mma_loop_lin(float acc[MT][NTP * 2][4],
    uint32_t aaddr, uint32_t amt, uint32_t baddr, uint32_t bnp)
{
#pragma unroll
    for (int mt = 0; mt < MT; mt++)
#pragma unroll
        for (int nt = 0; nt < NTP * 2; nt++)
#pragma unroll
            for (int i = 0; i < 4; i++) acc[mt][nt][i] = 0.0f;

#pragma unroll
    for (int kt = 0; kt < KT; kt++) {
        uint32_t ah[MT][4], bh[NTP][4];
#pragma unroll
        for (int mt = 0; mt < MT; mt++)
            LDSM4(ah[mt][0], ah[mt][1], ah[mt][2], ah[mt][3], aaddr + mt * amt + kt * 32);
#pragma unroll
        for (int np = 0; np < NTP; np++)
            LDSM4(bh[np][0], bh[np][1], bh[np][2], bh[np][3], baddr + np * bnp + kt * 32);
#pragma unroll
        for (int np = 0; np < NTP; np++)
#pragma unroll
            for (int mt = 0; mt < MT; mt++) {
                mma16816(acc[mt][2 * np],     ah[mt], bh[np][0], bh[np][1]);
                mma16816(acc[mt][2 * np + 1], ah[mt], bh[np][2], bh[np][3]);
            }
    }
}

// ---------------- swizzled mainloop (layers 2/3: XOR chunk^=(row&7)) ----------------
template <int MT, int NTP, int KT>
__device__ __forceinline__ void mma_loop_sw(float acc[MT][NTP * 2][4],
    uint32_t arow, uint32_t as, uint32_t acp, uint32_t amt,
    uint32_t brow, uint32_t bs, uint32_t bcp, uint32_t bnp)
{
#pragma unroll
    for (int mt = 0; mt < MT; mt++)
#pragma unroll
        for (int nt = 0; nt < NTP * 2; nt++)
#pragma unroll
            for (int i = 0; i < 4; i++) acc[mt][nt][i] = 0.0f;

#pragma unroll
    for (int kt = 0; kt < KT; kt++) {
        uint32_t ah[MT][4], bh[NTP][4];
        const uint32_t ac = (((uint32_t)(kt * 2) + acp) ^ as) << 4;
        const uint32_t bc = (((uint32_t)(kt * 2) + bcp) ^ bs) << 4;
#pragma unroll
        for (int mt = 0; mt < MT; mt++)
            LDSM4(ah[mt][0], ah[mt][1], ah[mt][2], ah[mt][3], arow + mt * amt + ac);
#pragma unroll
        for (int np = 0; np < NTP; np++)
            LDSM4(bh[np][0], bh[np][1], bh[np][2], bh[np][3], brow + np * bnp + bc);
#pragma unroll
        for (int np = 0; np < NTP; np++)
#pragma unroll
            for (int mt = 0; mt < MT; mt++) {
                mma16816(acc[mt][2 * np],     ah[mt], bh[np][0], bh[np][1]);
                mma16816(acc[mt][2 * np + 1], ah[mt], bh[np][2], bh[np][3]);
            }
    }
}

// epilogue: packed half2 bias + silu -> fp16 XOR-swizzled dest (RS-byte rows)
template <int MT, int NT, int RS>
__device__ __forceinline__ void epi_store_h2(float acc[MT][NT][4],
    const uint32_t* __restrict__ biash, uint32_t hbase, int rbase, int nbase, int lane)
{
    const int qr = lane >> 2, qk = (lane & 3) * 2;
#pragma unroll
    for (int mt = 0; mt < MT; mt++) {
        const int r0 = rbase + mt * 16 + qr;
        const int r1 = r0 + 8;
#pragma unroll
        for (int nt = 0; nt < NT; nt++) {
            const int col = nbase + nt * 8 + qk;
            const uint32_t ch = (uint32_t)(col >> 3);
            const uint32_t bb = biash[col >> 1];
            __half2 x0 = __hadd2(__floats2half2_rn(acc[mt][nt][0], acc[mt][nt][1]),
                                 *(const __half2*)&bb);
            __half2 x1 = __hadd2(__floats2half2_rn(acc[mt][nt][2], acc[mt][nt][3]),
                                 *(const __half2*)&bb);
            __half2 o0 = silu_h2(x0);
            __half2 o1 = silu_h2(x1);
            const uint32_t off0 = (uint32_t)(r0 * RS) + ((ch ^ (uint32_t)(r0 & 7)) << 4) + qk * 2;
            const uint32_t off1 = (uint32_t)(r1 * RS) + ((ch ^ (uint32_t)(r1 & 7)) << 4) + qk * 2;
            STS32(hbase + off0, *(uint32_t*)&o0);
            STS32(hbase + off1, *(uint32_t*)&o1);
        }
    }
}

// W1 fp32 [128][100] -> grouped-224 fp16; zero pad k in [100,112)
__device__ __forceinline__ void load_w1(const float* __restrict__ Wg,
                                        char* hi, int tid)
{
    for (int idx = tid; idx < 128 * 112; idx += THREADS) {
        int n = idx / 112, k = idx - n * 112;
        float v = (k < 100) ? __ldg(&Wg[n * 100 + k]) : 0.0f;
        *(__half*)(hi + rowoff224(n) + (uint32_t)k * 2) = __float2half_rn(v);
    }
}

// weights fp32 [N][K] -> XOR-swizzled fp16, RS-byte rows
template <int N, int K, int RS>
__device__ __forceinline__ void load_w_sw(const float* __restrict__ Wg,
                                          char* dst, int tid)
{
    for (int idx = tid; idx < N * K; idx += THREADS) {
        int n = idx / K, k = idx - n * K;
        uint32_t o = (uint32_t)(n * RS) + (((uint32_t)(k >> 3) ^ (uint32_t)(n & 7)) << 4)
                   + (uint32_t)(k & 7) * 2;
        *(__half*)(dst + o) = __float2half_rn(__ldg(&Wg[idx]));
    }
}

// cp.async one pre-converted X tile; 256 threads (t0 = quarter-tid)
__device__ __forceinline__ void stage_cp(const char* __restrict__ g, uint32_t sdst, int t0)
{
#pragma unroll
    for (int i = 0; i < 4; i++) {
        int off = (t0 + i * 256) * 16;
        if (off < XTILE_BYTES)
            asm volatile("cp.async.cg.shared.global [%0], [%1], 16;"
                         :: "r"(sdst + (uint32_t)off), "l"(g + off) : "memory");
    }
    asm volatile("cp.async.commit_group;" ::: "memory");
}

// ---------------- prepass: res fp32 -> fp16 grouped-224 tiles in global ----------------
__global__ void prep_x(const float* __restrict__ res, int ntiles)
{
    const int tt = blockIdx.x;
    if (tt >= ntiles) return;
    char* dst = g_xf16 + (size_t)tt * XTILE_BYTES;
    const int tid = threadIdx.x;
    for (int i = tid; i < XTILE_BYTES / 16; i += 256)
        *(uint4*)(dst + (size_t)i * 16) = make_uint4(0u, 0u, 0u, 0u);
    __syncthreads();
    const float4* src = (const float4*)(res + (size_t)tt * 6400);
    for (int gi = tid; gi < 1600; gi += 256) {
        int r = gi / 25, j = gi - r * 25;
        float4 v = __ldg(src + gi);
        __half2 h0 = __floats2half2_rn(v.x, v.y);
        __half2 h1 = __floats2half2_rn(v.z, v.w);
        *(uint2*)(dst + rowoff224(r) + (uint32_t)j * 8) =
            make_uint2(*(uint32_t*)&h0, *(uint32_t*)&h1);
    }
}

__global__ void __launch_bounds__(THREADS, 1) mlp_fused(
    const float* __restrict__ W1, const float* __restrict__ b1,
    const float* __restrict__ W2, const float* __restrict__ b2,
    const float* __restrict__ W3, const float* __restrict__ b3,
    const float* __restrict__ W4, const float* __restrict__ b4,
    const float* __restrict__ coupling,
    float* __restrict__ act_out, float* __restrict__ raw_out)
{
    extern __shared__ char smem[];
    const uint32_t sb = smem_u32(smem);
    const int tid = threadIdx.x, lane = tid & 31, wid = tid >> 5;
    const int qtr = wid >> 3, hwid = wid & 7, qtid = tid & 255;
    const int barid = qtr + 1;
    const int c = blockIdx.x % 6;
    const int grp = blockIdx.x / 6;          // 0..127, 2048 rows each

    const uint32_t qbs = sb + qtr * ACT_STRIDE;
    uint32_t* b1h = (uint32_t*)(smem + B1H);
    uint32_t* b2h = (uint32_t*)(smem + B2H);
    float* b3s  = (float*)(smem + B3S);
    float* w4s  = (float*)(smem + W4S);
    float* b4s  = (float*)(smem + B4S);
    int*   flag = (int*)(smem + FLAG);

    // ---- first X tile per quarter, then shared weights (ONE copy per SM) ----
    const int ht0 = grp * 32 + qtr;           // half-tile index of quarter's tile 0
    stage_cp(g_xf16 + (size_t)ht0 * XTILE_BYTES, qbs + X_OFF, qtid);

    load_w1(W1 + (size_t)c * 128 * 100, smem + W1_HI, tid);
    load_w_sw<64, 128, 256>(W2 + (size_t)c * 64 * 128, smem + W2_OFF, tid);
    load_w_sw<32, 64, 128>(W3 + (size_t)c * 32 * 64, smem + W3_OFF, tid);
    if (tid < 64) {
        __half2 h = __floats2half2_rn(__ldg(&b1[c * 128 + 2 * tid]),
                                      __ldg(&b1[c * 128 + 2 * tid + 1]));
        b1h[tid] = *(uint32_t*)&h;
    }
    if (tid < 32) {
        __half2 h = __floats2half2_rn(__ldg(&b2[c * 64 + 2 * tid]),
                                      __ldg(&b2[c * 64 + 2 * tid + 1]));
        b2h[tid] = *(uint32_t*)&h;
        b3s[tid] = __ldg(&b3[c * 32 + tid]);
        w4s[tid] = __ldg(&W4[c * 32 + tid]);
    }
    if (tid == 0) b4s[0] = __ldg(&b4[c]);

    CP_WAIT();
    __syncthreads();

    const int g = lane >> 3, rl = lane & 7;
    const uint32_t sA = (uint32_t)rl;
    const uint32_t acp = (uint32_t)(g >> 1);
    const uint32_t bcp = (uint32_t)(g & 1);

    for (int t = 0; t < GTILES; t++) {
        const int row0 = grp * 2048 + t * 256 + qtr * 64;

        // ---- layer 1 (main + epi fused: H1 is a separate region now) ----
        {
            float acc1[2][4][4];
            const int ar = (hwid >> 2) * 32 + (g & 1) * 8 + rl;
            const int br = (hwid & 3) * 32 + (g >> 1) * 8 + rl;
            mma_loop_lin<2, 2, 7>(acc1,
                qbs + X_OFF + rowoff224(ar) + (g >> 1) * 16, 3616,
                sb + W1_HI + rowoff224(br) + (g & 1) * 16, 3616);
            epi_store_h2<2, 4, 256>(acc1, b1h, qbs + H1_OFF,
                                    (hwid >> 2) * 32, (hwid & 3) * 32, lane);
        }
        BARQ(barid);   // H1 ready; X fully consumed -> prefetch next tile now

        if (t + 1 < GTILES)
            stage_cp(g_xf16 + (size_t)(ht0 + (t + 1) * 4) * XTILE_BYTES,
                     qbs + X_OFF, qtid);    // overlaps L2 + L3

        // ---- layer 2: H1[64x128] @ W2[64x128]^T -> H2[64x64] ----
        {
            float acc[1][4][4];
            const int ar = (hwid >> 1) * 16 + (g & 1) * 8 + rl;
            const int br = (hwid & 1) * 32 + (g >> 1) * 8 + rl;
            mma_loop_sw<1, 2, 8>(acc,
                qbs + H1_OFF + (uint32_t)ar * 256, sA, acp, 0,
                sb + W2_OFF + (uint32_t)br * 256, sA, bcp, 4096);
            epi_store_h2<1, 4, 128>(acc, b2h, qbs + H2_OFF,
                                    (hwid >> 1) * 16, (hwid & 1) * 32, lane);
        }
        BARQ(barid);   // H2 ready

        // ---- layer 3 + 4 (warps 0-3 of quarter) ----
        if (hwid < 4) {
            float acc[1][4][4];
            const int rbase = hwid * 16;
            const int ar = rbase + (g & 1) * 8 + rl;
            const int br = (g >> 1) * 8 + rl;
            mma_loop_sw<1, 2, 4>(acc,
                qbs + H2_OFF + (uint32_t)ar * 128, sA, acp, 0,
                sb + W3_OFF + (uint32_t)br * 128, sA, bcp, 2048);
            const int qr = lane >> 2, qk = (lane & 3) * 2;
            float p0 = 0.0f, p1 = 0.0f;
#pragma unroll
            for (int nt = 0; nt < 4; nt++) {
                const int col = nt * 8 + qk;
                const float w0 = w4s[col], w1 = w4s[col + 1];
                const float c0 = b3s[col], c1 = b3s[col + 1];
                p0 += silu_f(acc[0][nt][0] + c0) * w0 + silu_f(acc[0][nt][1] + c1) * w1;
                p1 += silu_f(acc[0][nt][2] + c0) * w0 + silu_f(acc[0][nt][3] + c1) * w1;
            }
            p0 += __shfl_xor_sync(0xFFFFFFFFu, p0, 1);
            p0 += __shfl_xor_sync(0xFFFFFFFFu, p0, 2);
            p1 += __shfl_xor_sync(0xFFFFFFFFu, p1, 1);
            p1 += __shfl_xor_sync(0xFFFFFFFFu, p1, 2);
            if ((lane & 3) == 0) {
                const float bb = b4s[0];
                raw_out[(size_t)(row0 + rbase + qr) * 6 + c]     = p0 + bb;
                raw_out[(size_t)(row0 + rbase + qr + 8) * 6 + c] = p1 + bb;
            }
        }
        CP_WAIT();     // all threads issued the prefetch; drain before reuse
        BARQ(barid);   // next X visible to the whole quarter; H2 consumed
    }

    // ---- last CTA of this row-group: sigmoid + coupling for 2048 rows ----
    __threadfence();
    __syncthreads();
    if (tid == 0) *flag = atomicAdd(&g_cnt[grp], 1);
    __syncthreads();
    if (*flag != 5) return;
    if (tid == 0) g_cnt[grp] = 0;
    __threadfence();

    const float decay[6] = {0.9f, 0.93f, 0.85f, 0.97f, 0.88f, 0.94f};
#pragma unroll
    for (int rr = 0; rr < 2; rr++) {
        const int row = grp * 2048 + rr * 1024 + tid;
        float a[6];
#pragma unroll
        for (int i = 0; i < 6; i++) {
            float r = raw_out[(size_t)row * 6 + i];
            a[i] = __fdividef(1.0f, 1.0f + __expf(-r));
        }
#pragma unroll
        for (int it = 0; it < 5; it++) {
#pragma unroll
            for (int i = 0; i < 6; i++) a[i] *= decay[i];
            float na[6];
#pragma unroll
            for (int i = 0; i < 6; i++) {
                float s = 0.0f;
#pragma unroll
                for (int j = 0; j < 6; j++)
                    s += __ldg(&coupling[i * 6 + j]) * __sinf(a[j] - a[i]);
                na[i] = a[i] + 0.02f * s;
            }
#pragma unroll
            for (int i = 0; i < 6; i++) a[i] = fminf(fmaxf(na[i], 0.0f), 1.0f);
        }
#pragma unroll
        for (int i = 0; i < 6; i++) act_out[(size_t)row * 6 + i] = a[i];
    }
}

extern "C" void kernel_launch(void* const* d_in, const int* in_sizes, int n_in,
                              void* d_out, int out_size)
{
    const float* res      = (const float*)d_in[0];
    const float* W1       = (const float*)d_in[1];
    const float* b1       = (const float*)d_in[2];
    const float* W2       = (const float*)d_in[3];
    const float* b2       = (const float*)d_in[4];
    const float* W3       = (const float*)d_in[5];
    const float* b3       = (const float*)d_in[6];
    const float* W4       = (const float*)d_in[7];
    const float* b4       = (const float*)d_in[8];
    const float* coupling = (const float*)d_in[9];

    int Btot = in_sizes[0] / 100;
    float* act = (float*)d_out;
    float* raw = act + (size_t)Btot * 6;
    int ntiles = Btot / 64;

    prep_x<<<ntiles, 256>>>(res, ntiles);
    cudaFuncSetAttribute(mlp_fused, cudaFuncAttributeMaxDynamicSharedMemorySize, SMEM_BYTES);
    mlp_fused<<<NBLOCKS, THREADS, SMEM_BYTES>>>(W1, b1, W2, b2, W3, b3, W4, b4,
                                                coupling, act, raw);
}

// round 15
// speedup vs baseline: 1.0678x; 1.0678x over previous
#include <cuda_runtime.h>
#include <cuda_fp16.h>
#include <cstdint>

#define THREADS 512
#define GTILES  8
#define GROUPS  256                 // 2048 tiles / 8
#define NBLOCKS (6 * GROUPS)        // 1536
#define XTILE_BYTES 14464           // one 64-row fp16 X tile, grouped-224 layout

// ---------------- smem layout (bytes), per CTA (2 CTAs/SM) ----------------
#define ACT_STRIDE 24576    // per-half activation block (region0 + H2)
#define XH1_OFF 0           // 16384 (X grouped-224 aliased with H1 64x256B swz)
#define H2_OFF  16384       // 8192  (64 x 128B swz)
#define W1_HI   49152       // 28928 (128 rows grouped-224)
#define W2_OFF  78080       // 16384 (64 x 256B swz)
#define W3_OFF  94464       // 4096  (32 x 128B swz)
#define B1H     98560       // half2 [64]  (256B)
#define B2H     98816       // half2 [32]  (128B)
#define B3S     98944       // fp32 [32]
#define W4S     99072       // fp32 [32]
#define B4S     99200       // fp32 [1]
#define FLAG    99204       // int
#define SMEM_BYTES 99328    // x2 = 198656 <= SM smem

__device__ int g_cnt[GROUPS];                       // zero-init; restored each launch
__device__ __align__(16) char g_xf16[4096 * XTILE_BYTES];   // prepass fp16 X tiles

__device__ __forceinline__ uint32_t smem_u32(const void* p) {
    uint32_t a;
    asm("{ .reg .u64 t; cvta.to.shared.u64 t, %1; cvt.u32.u64 %0, t; }"
        : "=r"(a) : "l"(p));
    return a;
}

__host__ __device__ __forceinline__ uint32_t rowoff224(int r) {
    return (uint32_t)((r >> 3) * 1808 + (r & 7) * 224 + ((r & 4) << 2));
}

#define LDSM4(R0, R1, R2, R3, ADDR)                                        \
    asm volatile("ldmatrix.sync.aligned.m8n8.x4.shared.b16 {%0,%1,%2,%3},[%4];" \
                 : "=r"(R0), "=r"(R1), "=r"(R2), "=r"(R3) : "r"(ADDR))

#define STS32(ADDR, V) \
    asm volatile("st.shared.b32 [%0], %1;" :: "r"(ADDR), "r"(V) : "memory")

#define BARH(id) asm volatile("bar.sync %0, 256;" :: "r"(id) : "memory")
#define CP_WAIT() asm volatile("cp.async.wait_group 0;" ::: "memory")

__device__ __forceinline__ void mma16816(float c[4], const uint32_t a[4],
                                         uint32_t b0, uint32_t b1) {
    asm volatile(
        "mma.sync.aligned.m16n8k16.row.col.f32.f16.f16.f32 "
        "{%0,%1,%2,%3},{%4,%5,%6,%7},{%8,%9},{%0,%1,%2,%3};\n"
        : "+f"(c[0]), "+f"(c[1]), "+f"(c[2]), "+f"(c[3])
        : "r"(a[0]), "r"(a[1]), "r"(a[2]), "r"(a[3]), "r"(b0), "r"(b1));
}

// k8 MMA for the layer-1 K tail
__device__ __forceinline__ void mma16808(float c[4], uint32_t a0, uint32_t a1,
                                         uint32_t b0) {
    asm volatile(
        "mma.sync.aligned.m16n8k8.row.col.f32.f16.f16.f32 "
        "{%0,%1,%2,%3},{%4,%5},{%6},{%0,%1,%2,%3};\n"
        : "+f"(c[0]), "+f"(c[1]), "+f"(c[2]), "+f"(c[3])
        : "r"(a0), "r"(a1), "r"(b0));
}

// fp32 silu via MUFU tanh
__device__ __forceinline__ float silu_f(float x) {
    float t;
    asm("tanh.approx.f32 %0, %1;" : "=f"(t) : "f"(0.5f * x));
    return x * fmaf(0.5f, t, 0.5f);
}

// packed half2 silu via tanh.approx.f16x2
__device__ __forceinline__ __half2 silu_h2(__half2 x) {
    const __half2 h05 = __floats2half2_rn(0.5f, 0.5f);
    __half2 t = __hmul2(x, h05);
    uint32_t th;
    asm("tanh.approx.f16x2 %0, %1;" : "=r"(th) : "r"(*(uint32_t*)&t));
    __half2 s = __hfma2(*(__half2*)&th, h05, h05);
    return __hmul2(x, s);
}

// ---------------- linear mainloop (layer 1: grouped-224 A and B) ----------------
template <int MT, int NTP, int KT>
__device__ __forceinline__ void mma_loop_lin(float acc[MT][NTP * 2][4],
    uint32_t aaddr, uint32_t amt, uint32_t baddr, uint32_t bnp)
{
#pragma unroll
    for (int kt = 0; kt < KT; kt++) {
        uint32_t ah[MT][4], bh[NTP][4];
#pragma unroll
        for (int mt = 0; mt < MT; mt++)
            LDSM4(ah[mt][0], ah[mt][1], ah[mt][2], ah[mt][3], aaddr + mt * amt + kt * 32);
#pragma unroll
        for (int np = 0; np < NTP; np++)
            LDSM4(bh[np][0], bh[np][1], bh[np][2], bh[np][3], baddr + np * bnp + kt * 32);
#pragma unroll
        for (int np = 0; np < NTP; np++)
#pragma unroll
            for (int mt = 0; mt < MT; mt++) {
                mma16816(acc[mt][2 * np],     ah[mt], bh[np][0], bh[np][1]);
                mma16816(acc[mt][2 * np + 1], ah[mt], bh[np][2], bh[np][3]);
            }
    }
}

// ---------------- swizzled mainloop (layers 2/3: XOR chunk^=(row&7)) ----------------
template <int MT, int NTP, int KT>
__device__ __forceinline__ void mma_loop_sw(float acc[MT][NTP * 2][4],
    uint32_t arow, uint32_t as, uint32_t acp, uint32_t amt,
    uint32_t brow, uint32_t bs, uint32_t bcp, uint32_t bnp)
{
#pragma unroll
    for (int mt = 0; mt < MT; mt++)
#pragma unroll
        for (int nt = 0; nt < NTP * 2; nt++)
#pragma unroll
            for (int i = 0; i < 4; i++) acc[mt][nt][i] = 0.0f;

#pragma unroll
    for (int kt = 0; kt < KT; kt++) {
        uint32_t ah[MT][4], bh[NTP][4];
        const uint32_t ac = (((uint32_t)(kt * 2) + acp) ^ as) << 4;
        const uint32_t bc = (((uint32_t)(kt * 2) + bcp) ^ bs) << 4;
#pragma unroll
        for (int mt = 0; mt < MT; mt++)
            LDSM4(ah[mt][0], ah[mt][1], ah[mt][2], ah[mt][3], arow + mt * amt + ac);
#pragma unroll
        for (int np = 0; np < NTP; np++)
            LDSM4(bh[np][0], bh[np][1], bh[np][2], bh[np][3], brow + np * bnp + bc);
#pragma unroll
        for (int np = 0; np < NTP; np++)
#pragma unroll
            for (int mt = 0; mt < MT; mt++) {
                mma16816(acc[mt][2 * np],     ah[mt], bh[np][0], bh[np][1]);
                mma16816(acc[mt][2 * np + 1], ah[mt], bh[np][2], bh[np][3]);
            }
    }
}

// epilogue: packed half2 bias + silu -> fp16 XOR-swizzled dest (RS-byte rows)
template <int MT, int NT, int RS>
__device__ __forceinline__ void epi_store_h2(float acc[MT][NT][4],
    const uint32_t* __restrict__ biash, uint32_t hbase, int rbase, int nbase, int lane)
{
    const int qr = lane >> 2, qk = (lane & 3) * 2;
#pragma unroll
    for (int mt = 0; mt < MT; mt++) {
        const int r0 = rbase + mt * 16 + qr;
        const int r1 = r0 + 8;
#pragma unroll
        for (int nt = 0; nt < NT; nt++) {
            const int col = nbase + nt * 8 + qk;
            const uint32_t ch = (uint32_t)(col >> 3);
            const uint32_t bb = biash[col >> 1];
            __half2 x0 = __hadd2(__floats2half2_rn(acc[mt][nt][0], acc[mt][nt][1]),
                                 *(const __half2*)&bb);
            __half2 x1 = __hadd2(__floats2half2_rn(acc[mt][nt][2], acc[mt][nt][3]),
                                 *(const __half2*)&bb);
            __half2 o0 = silu_h2(x0);
            __half2 o1 = silu_h2(x1);
            const uint32_t off0 = (uint32_t)(r0 * RS) + ((ch ^ (uint32_t)(r0 & 7)) << 4) + qk * 2;
            const uint32_t off1 = (uint32_t)(r1 * RS) + ((ch ^ (uint32_t)(r1 & 7)) << 4) + qk * 2;
            STS32(hbase + off0, *(uint32_t*)&o0);
            STS32(hbase + off1, *(uint32_t*)&o1);
        }
    }
}

// W1 fp32 [128][100] -> grouped-224 fp16; zero pad k in [100,112)
__device__ __forceinline__ void load_w1(const float* __restrict__ Wg,
                                        char* hi, int tid)
{
    for (int idx = tid; idx < 128 * 112; idx += THREADS) {
        int n = idx / 112, k = idx - n * 112;
        float v = (k < 100) ? __ldg(&Wg[n * 100 + k]) : 0.0f;
        *(__half*)(hi + rowoff224(n) + (uint32_t)k * 2) = __float2half_rn(v);
    }
}

// weights fp32 [N][K] -> XOR-swizzled fp16, RS-byte rows
template <int N, int K, int RS>
__device__ __forceinline__ void load_w_sw(const float* __restrict__ Wg,
                                          char* dst, int tid)
{
    for (int idx = tid; idx < N * K; idx += THREADS) {
        int n = idx / K, k = idx - n * K;
        uint32_t o = (uint32_t)(n * RS) + (((uint32_t)(k >> 3) ^ (uint32_t)(n & 7)) << 4)
                   + (uint32_t)(k & 7) * 2;
        *(__half*)(dst + o) = __float2half_rn(__ldg(&Wg[idx]));
    }
}

// cp.async one pre-converted X tile; NTHR participating threads (t0-based)
template <int NTHR>
__device__ __forceinline__ void stage_cp(const char* __restrict__ g, uint32_t sdst, int t0)
{
#pragma unroll
    for (int i = 0; i < (XTILE_BYTES / 16 + NTHR - 1) / NTHR; i++) {
        int off = (t0 + i * NTHR) * 16;
        if (off < XTILE_BYTES)
            asm volatile("cp.async.cg.shared.global [%0], [%1], 16;"
                         :: "r"(sdst + (uint32_t)off), "l"(g + off) : "memory");
    }
    asm volatile("cp.async.commit_group;" ::: "memory");
}

// ---------------- prepass: res fp32 -> fp16 grouped-224 tiles in global ----------------
__global__ void prep_x(const float* __restrict__ res, int ntiles)
{
    const int tt = blockIdx.x;
    if (tt >= ntiles) return;
    char* dst = g_xf16 + (size_t)tt * XTILE_BYTES;
    const int tid = threadIdx.x;
    for (int i = tid; i < XTILE_BYTES / 16; i += 256)
        *(uint4*)(dst + (size_t)i * 16) = make_uint4(0u, 0u, 0u, 0u);
    __syncthreads();
    const float4* src = (const float4*)(res + (size_t)tt * 6400);
    for (int gi = tid; gi < 1600; gi += 256) {
        int r = gi / 25, j = gi - r * 25;
        float4 v = __ldg(src + gi);
        __half2 h0 = __floats2half2_rn(v.x, v.y);
        __half2 h1 = __floats2half2_rn(v.z, v.w);
        *(uint2*)(dst + rowoff224(r) + (uint32_t)j * 8) =
            make_uint2(*(uint32_t*)&h0, *(uint32_t*)&h1);
    }
}

__global__ void __launch_bounds__(THREADS, 2) mlp_fused(
    const float* __restrict__ W1, const float* __restrict__ b1,
    const float* __restrict__ W2, const float* __restrict__ b2,
    const float* __restrict__ W3, const float* __restrict__ b3,
    const float* __restrict__ W4, const float* __restrict__ b4,
    const float* __restrict__ coupling,
    float* __restrict__ act_out, float* __restrict__ raw_out)
{
    extern __shared__ char smem[];
    const uint32_t sb = smem_u32(smem);
    const int tid = threadIdx.x, lane = tid & 31, wid = tid >> 5;
    const int half = wid >> 3, hwid = wid & 7, htid = tid & 255;
    const int barid = half + 1;
    const int c = blockIdx.x % 6;
    const int grp = blockIdx.x / 6;

    const uint32_t hbs = sb + half * ACT_STRIDE;
    uint32_t* b1h = (uint32_t*)(smem + B1H);
    uint32_t* b2h = (uint32_t*)(smem + B2H);
    float* b3s  = (float*)(smem + B3S);
    float* w4s  = (float*)(smem + W4S);
    float* b4s  = (float*)(smem + B4S);
    int*   flag = (int*)(smem + FLAG);

    // ---- first X tile via cp.async, then weights + packed biases ----
    stage_cp<256>(g_xf16 + (size_t)(grp * 16 + half) * XTILE_BYTES, hbs + XH1_OFF, htid);

    load_w1(W1 + (size_t)c * 128 * 100, smem + W1_HI, tid);
    load_w_sw<64, 128, 256>(W2 + (size_t)c * 64 * 128, smem + W2_OFF, tid);
    load_w_sw<32, 64, 128>(W3 + (size_t)c * 32 * 64, smem + W3_OFF, tid);
    if (tid < 64) {
        __half2 h = __floats2half2_rn(__ldg(&b1[c * 128 + 2 * tid]),
                                      __ldg(&b1[c * 128 + 2 * tid + 1]));
        b1h[tid] = *(uint32_t*)&h;
    }
    if (tid < 32) {
        __half2 h = __floats2half2_rn(__ldg(&b2[c * 64 + 2 * tid]),
                                      __ldg(&b2[c * 64 + 2 * tid + 1]));
        b2h[tid] = *(uint32_t*)&h;
        b3s[tid] = __ldg(&b3[c * 32 + tid]);
        w4s[tid] = __ldg(&W4[c * 32 + tid]);
    }
    if (tid == 0) b4s[0] = __ldg(&b4[c]);

    CP_WAIT();
    __syncthreads();

    const int g = lane >> 3, rl = lane & 7;
    const uint32_t sA = (uint32_t)rl;
    const uint32_t acp = (uint32_t)(g >> 1);
    const uint32_t bcp = (uint32_t)(g & 1);

    // layer-1 lane-resolved offsets (mainloop + k8 tail)
    const int l1_rb = (hwid >> 2) * 32, l1_nb = (hwid & 3) * 32;
    const int ar1 = l1_rb + (g & 1) * 8 + rl;
    const int br1 = l1_nb + (g >> 1) * 8 + rl;
    const uint32_t a1main = rowoff224(ar1) + (g >> 1) * 16;
    const uint32_t b1main = rowoff224(br1) + (g & 1) * 16;
    // tail A: lanes 0-15 -> mt0 rows rb..rb+15; lanes 16-31 -> mt1 rows rb+16..rb+31
    const int arT = l1_rb + (lane & 15) + ((lane >> 4) << 4);   // FIXED: <<4 (was <<5)
    const uint32_t a1tail = rowoff224(arT) + 192;       // col 96 (x2 bytes)
    // tail B: lanes 0-31 -> n-rows nb..nb+31
    const uint32_t b1tail = rowoff224(l1_nb + lane) + 192;

    for (int t = 0; t < GTILES; t++) {
        const int row0 = grp * 1024 + t * 128 + half * 64;

        // ---- layer 1 mainloop: X[64x100] @ W1[128x100]^T (6xk16 + 1xk8) ----
        float acc1[2][4][4];
#pragma unroll
        for (int mt = 0; mt < 2; mt++)
#pragma unroll
            for (int nt = 0; nt < 4; nt++)
#pragma unroll
                for (int i = 0; i < 4; i++) acc1[mt][nt][i] = 0.0f;
        mma_loop_lin<2, 2, 6>(acc1,
            hbs + XH1_OFF + a1main, 3616,
            sb + W1_HI + b1main, 3616);
        {   // k8 tail: cols 96..103 (100..103 are zero)
            uint32_t aa[4], bb[4];
            LDSM4(aa[0], aa[1], aa[2], aa[3], hbs + XH1_OFF + a1tail);
            LDSM4(bb[0], bb[1], bb[2], bb[3], sb + W1_HI + b1tail);
#pragma unroll
            for (int nt = 0; nt < 4; nt++) {
                mma16808(acc1[0][nt], aa[0], aa[1], bb[nt]);
                mma16808(acc1[1][nt], aa[2], aa[3], bb[nt]);
            }
        }
        BARH(barid);   // all X reads done -> region0 reusable for H1

        // ---- layer 1 epilogue: H1 overwrites X region ----
        epi_store_h2<2, 4, 256>(acc1, b1h, hbs + XH1_OFF, l1_rb, l1_nb, lane);
        BARH(barid);   // H1 ready

        // ---- layer 2: H1[64x128] @ W2[64x128]^T -> H2[64x64] ----
        {
            float acc[1][4][4];
            const int ar = (hwid >> 1) * 16 + (g & 1) * 8 + rl;
            const int br = (hwid & 1) * 32 + (g >> 1) * 8 + rl;
            mma_loop_sw<1, 2, 8>(acc,
                hbs + XH1_OFF + (uint32_t)ar * 256, sA, acp, 0,
                sb + W2_OFF + (uint32_t)br * 256, sA, bcp, 4096);
            epi_store_h2<1, 4, 128>(acc, b2h, hbs + H2_OFF,
                                    (hwid >> 1) * 16, (hwid & 1) * 32, lane);
        }
        BARH(barid);   // H2 ready; H1 reads done -> region0 free

        // ---- layer 3+4 (warps 0-3) in parallel with next-X prefetch (warps 4-7) ----
        if (hwid < 4) {
            float acc[1][4][4];
            const int rbase = hwid * 16;
            const int ar = rbase + (g & 1) * 8 + rl;
            const int br = (g >> 1) * 8 + rl;
            mma_loop_sw<1, 2, 4>(acc,
                hbs + H2_OFF + (uint32_t)ar * 128, sA, acp, 0,
                sb + W3_OFF + (uint32_t)br * 128, sA, bcp, 2048);
            const int qr = lane >> 2, qk = (lane & 3) * 2;
            float p0 = 0.0f, p1 = 0.0f;
#pragma unroll
            for (int nt = 0; nt < 4; nt++) {
                const int col = nt * 8 + qk;
                const float w0 = w4s[col], w1 = w4s[col + 1];
                const float c0 = b3s[col], c1 = b3s[col + 1];
                p0 += silu_f(acc[0][nt][0] + c0) * w0 + silu_f(acc[0][nt][1] + c1) * w1;
                p1 += silu_f(acc[0][nt][2] + c0) * w0 + silu_f(acc[0][nt][3] + c1) * w1;
            }
            p0 += __shfl_xor_sync(0xFFFFFFFFu, p0, 1);
            p0 += __shfl_xor_sync(0xFFFFFFFFu, p0, 2);
            p1 += __shfl_xor_sync(0xFFFFFFFFu, p1, 1);
            p1 += __shfl_xor_sync(0xFFFFFFFFu, p1, 2);
            if ((lane & 3) == 0) {
                const float bb = b4s[0];
                raw_out[(size_t)(row0 + rbase + qr) * 6 + c]     = p0 + bb;
                raw_out[(size_t)(row0 + rbase + qr + 8) * 6 + c] = p1 + bb;
            }
        } else {
            if (t + 1 < GTILES)
                stage_cp<128>(g_xf16 + (size_t)(grp * 16 + (t + 1) * 2 + half) * XTILE_BYTES,
                              hbs + XH1_OFF, htid - 128);
            CP_WAIT();
        }
        BARH(barid);   // next X ready
    }

    // ---- last CTA of this row-group: sigmoid + coupling for 1024 rows ----
    __threadfence();
    __syncthreads();
    if (tid == 0) *flag = atomicAdd(&g_cnt[grp], 1);
    __syncthreads();
    if (*flag != 5) return;
    if (tid == 0) g_cnt[grp] = 0;
    __threadfence();

    const float decay[6] = {0.9f, 0.93f, 0.85f, 0.97f, 0.88f, 0.94f};
#pragma unroll
    for (int rr = 0; rr < 2; rr++) {
        const int row = grp * 1024 + rr * 512 + tid;
        float a[6];
#pragma unroll
        for (int i = 0; i < 6; i++) {
            float r = raw_out[(size_t)row * 6 + i];
            a[i] = __fdividef(1.0f, 1.0f + __expf(-r));
        }
#pragma unroll
        for (int it = 0; it < 5; it++) {
#pragma unroll
            for (int i = 0; i < 6; i++) a[i] *= decay[i];
            float na[6];
#pragma unroll
            for (int i = 0; i < 6; i++) {
                float s = 0.0f;
#pragma unroll
                for (int j = 0; j < 6; j++)
                    s += __ldg(&coupling[i * 6 + j]) * __sinf(a[j] - a[i]);
                na[i] = a[i] + 0.02f * s;
            }
#pragma unroll
            for (int i = 0; i < 6; i++) a[i] = fminf(fmaxf(na[i], 0.0f), 1.0f);
        }
#pragma unroll
        for (int i = 0; i < 6; i++) act_out[(size_t)row * 6 + i] = a[i];
    }
}

extern "C" void kernel_launch(void* const* d_in, const int* in_sizes, int n_in,
                              void* d_out, int out_size)
{
    const float* res      = (const float*)d_in[0];
    const float* W1       = (const float*)d_in[1];
    const float* b1       = (const float*)d_in[2];
    const float* W2       = (const float*)d_in[3];
    const float* b2       = (const float*)d_in[4];
    const float* W3       = (const float*)d_in[5];
    const float* b3       = (const float*)d_in[6];
    const float* W4       = (const float*)d_in[7];
    const float* b4       = (const float*)d_in[8];
    const float* coupling = (const float*)d_in[9];

    int Btot = in_sizes[0] / 100;
    float* act = (float*)d_out;
    float* raw = act + (size_t)Btot * 6;
    int ntiles = Btot / 64;

    prep_x<<<ntiles, 256>>>(res, ntiles);
    cudaFuncSetAttribute(mlp_fused, cudaFuncAttributeMaxDynamicSharedMemorySize, SMEM_BYTES);
    mlp_fused<<<NBLOCKS, THREADS, SMEM_BYTES>>>(W1, b1, W2, b2, W3, b3, W4, b4,
                                                coupling, act, raw);
}

// round 16
// speedup vs baseline: 1.1059x; 1.0357x over previous
#include <cuda_runtime.h>
#include <cuda_fp16.h>
#include <cstdint>

#define THREADS 512
#define GTILES  8
#define GROUPS  256                 // row-groups of 1024 rows
#define NBLOCKS 288                 // persistent: 6 chambers x 48 CTAs (single wave)
#define XTILE_BYTES 14464           // one 64-row fp16 X tile, grouped-224 layout

// ---------------- smem layout (bytes), per CTA (2 CTAs/SM) ----------------
#define ACT_STRIDE 24576    // per-half activation block (region0 + H2)
#define XH1_OFF 0           // 16384 (X grouped-224 aliased with H1 64x256B swz)
#define H2_OFF  16384       // 8192  (64 x 128B swz)
#define W1_HI   49152       // 28928 (128 rows grouped-224)
#define W2_OFF  78080       // 16384 (64 x 256B swz)
#define W3_OFF  94464       // 4096  (32 x 128B swz)
#define B1H     98560       // half2 [64]  (256B)
#define B2H     98816       // half2 [32]  (128B)
#define B3S     98944       // fp32 [32]
#define W4S     99072       // fp32 [32]
#define B4S     99200       // fp32 [1]
#define WRK     99204       // int [3]: flag, cur, nxt
#define SMEM_BYTES 99328    // x2 = 198656 <= SM smem

__device__ int g_cnt[GROUPS];   // per-group completion counters (self-resetting)
__device__ int g_work[6];       // per-chamber group-steal counters (zeroed by prep_x)
__device__ __align__(16) char g_xf16[4096 * XTILE_BYTES];   // prepass fp16 X tiles

__device__ __forceinline__ uint32_t smem_u32(const void* p) {
    uint32_t a;
    asm("{ .reg .u64 t; cvta.to.shared.u64 t, %1; cvt.u32.u64 %0, t; }"
        : "=r"(a) : "l"(p));
    return a;
}

__host__ __device__ __forceinline__ uint32_t rowoff224(int r) {
    return (uint32_t)((r >> 3) * 1808 + (r & 7) * 224 + ((r & 4) << 2));
}

#define LDSM4(R0, R1, R2, R3, ADDR)                                        \
    asm volatile("ldmatrix.sync.aligned.m8n8.x4.shared.b16 {%0,%1,%2,%3},[%4];" \
                 : "=r"(R0), "=r"(R1), "=r"(R2), "=r"(R3) : "r"(ADDR))

#define STS32(ADDR, V) \
    asm volatile("st.shared.b32 [%0], %1;" :: "r"(ADDR), "r"(V) : "memory")

#define BARH(id) asm volatile("bar.sync %0, 256;" :: "r"(id) : "memory")
#define CP_WAIT() asm volatile("cp.async.wait_group 0;" ::: "memory")

__device__ __forceinline__ void mma16816(float c[4], const uint32_t a[4],
                                         uint32_t b0, uint32_t b1) {
    asm volatile(
        "mma.sync.aligned.m16n8k16.row.col.f32.f16.f16.f32 "
        "{%0,%1,%2,%3},{%4,%5,%6,%7},{%8,%9},{%0,%1,%2,%3};\n"
        : "+f"(c[0]), "+f"(c[1]), "+f"(c[2]), "+f"(c[3])
        : "r"(a[0]), "r"(a[1]), "r"(a[2]), "r"(a[3]), "r"(b0), "r"(b1));
}

__device__ __forceinline__ void mma16808(float c[4], uint32_t a0, uint32_t a1,
                                         uint32_t b0) {
    asm volatile(
        "mma.sync.aligned.m16n8k8.row.col.f32.f16.f16.f32 "
        "{%0,%1,%2,%3},{%4,%5},{%6},{%0,%1,%2,%3};\n"
        : "+f"(c[0]), "+f"(c[1]), "+f"(c[2]), "+f"(c[3])
        : "r"(a0), "r"(a1), "r"(b0));
}

__device__ __forceinline__ float silu_f(float x) {
    float t;
    asm("tanh.approx.f32 %0, %1;" : "=f"(t) : "f"(0.5f * x));
    return x * fmaf(0.5f, t, 0.5f);
}

__device__ __forceinline__ __half2 silu_h2(__half2 x) {
    const __half2 h05 = __floats2half2_rn(0.5f, 0.5f);
    __half2 t = __hmul2(x, h05);
    uint32_t th;
    asm("tanh.approx.f16x2 %0, %1;" : "=r"(th) : "r"(*(uint32_t*)&t));
    __half2 s = __hfma2(*(__half2*)&th, h05, h05);
    return __hmul2(x, s);
}

// ---------------- linear mainloop (layer 1: grouped-224 A and B) ----------------
template <int MT, int NTP, int KT>
__device__ __forceinline__ void mma_loop_lin(float acc[MT][NTP * 2][4],
    uint32_t aaddr, uint32_t amt, uint32_t baddr, uint32_t bnp)
{
#pragma unroll
    for (int kt = 0; kt < KT; kt++) {
        uint32_t ah[MT][4], bh[NTP][4];
#pragma unroll
        for (int mt = 0; mt < MT; mt++)
            LDSM4(ah[mt][0], ah[mt][1], ah[mt][2], ah[mt][3], aaddr + mt * amt + kt * 32);
#pragma unroll
        for (int np = 0; np < NTP; np++)
            LDSM4(bh[np][0], bh[np][1], bh[np][2], bh[np][3], baddr + np * bnp + kt * 32);
#pragma unroll
        for (int np = 0; np < NTP; np++)
#pragma unroll
            for (int mt = 0; mt < MT; mt++) {
                mma16816(acc[mt][2 * np],     ah[mt], bh[np][0], bh[np][1]);
                mma16816(acc[mt][2 * np + 1], ah[mt], bh[np][2], bh[np][3]);
            }
    }
}

// ---------------- swizzled mainloop (layers 2/3: XOR chunk^=(row&7)) ----------------
template <int MT, int NTP, int KT>
__device__ __forceinline__ void mma_loop_sw(float acc[MT][NTP * 2][4],
    uint32_t arow, uint32_t as, uint32_t acp, uint32_t amt,
    uint32_t brow, uint32_t bs, uint32_t bcp, uint32_t bnp)
{
#pragma unroll
    for (int mt = 0; mt < MT; mt++)
#pragma unroll
        for (int nt = 0; nt < NTP * 2; nt++)
#pragma unroll
            for (int i = 0; i < 4; i++) acc[mt][nt][i] = 0.0f;

#pragma unroll
    for (int kt = 0; kt < KT; kt++) {
        uint32_t ah[MT][4], bh[NTP][4];
        const uint32_t ac = (((uint32_t)(kt * 2) + acp) ^ as) << 4;
        const uint32_t bc = (((uint32_t)(kt * 2) + bcp) ^ bs) << 4;
#pragma unroll
        for (int mt = 0; mt < MT; mt++)
            LDSM4(ah[mt][0], ah[mt][1], ah[mt][2], ah[mt][3], arow + mt * amt + ac);
#pragma unroll
        for (int np = 0; np < NTP; np++)
            LDSM4(bh[np][0], bh[np][1], bh[np][2], bh[np][3], brow + np * bnp + bc);
#pragma unroll
        for (int np = 0; np < NTP; np++)
#pragma unroll
            for (int mt = 0; mt < MT; mt++) {
                mma16816(acc[mt][2 * np],     ah[mt], bh[np][0], bh[np][1]);
                mma16816(acc[mt][2 * np + 1], ah[mt], bh[np][2], bh[np][3]);
            }
    }
}

// epilogue: packed half2 bias + silu -> fp16 XOR-swizzled dest (RS-byte rows)
template <int MT, int NT, int RS>
__device__ __forceinline__ void epi_store_h2(float acc[MT][NT][4],
    const uint32_t* __restrict__ biash, uint32_t hbase, int rbase, int nbase, int lane)
{
    const int qr = lane >> 2, qk = (lane & 3) * 2;
#pragma unroll
    for (int mt = 0; mt < MT; mt++) {
        const int r0 = rbase + mt * 16 + qr;
        const int r1 = r0 + 8;
#pragma unroll
        for (int nt = 0; nt < NT; nt++) {
            const int col = nbase + nt * 8 + qk;
            const uint32_t ch = (uint32_t)(col >> 3);
            const uint32_t bb = biash[col >> 1];
            __half2 x0 = __hadd2(__floats2half2_rn(acc[mt][nt][0], acc[mt][nt][1]),
                                 *(const __half2*)&bb);
            __half2 x1 = __hadd2(__floats2half2_rn(acc[mt][nt][2], acc[mt][nt][3]),
                                 *(const __half2*)&bb);
            __half2 o0 = silu_h2(x0);
            __half2 o1 = silu_h2(x1);
            const uint32_t off0 = (uint32_t)(r0 * RS) + ((ch ^ (uint32_t)(r0 & 7)) << 4) + qk * 2;
            const uint32_t off1 = (uint32_t)(r1 * RS) + ((ch ^ (uint32_t)(r1 & 7)) << 4) + qk * 2;
            STS32(hbase + off0, *(uint32_t*)&o0);
            STS32(hbase + off1, *(uint32_t*)&o1);
        }
    }
}

// W1 fp32 [128][100] -> grouped-224 fp16; zero pad k in [100,112)
__device__ __forceinline__ void load_w1(const float* __restrict__ Wg,
                                        char* hi, int tid)
{
    for (int idx = tid; idx < 128 * 112; idx += THREADS) {
        int n = idx / 112, k = idx - n * 112;
        float v = (k < 100) ? __ldg(&Wg[n * 100 + k]) : 0.0f;
        *(__half*)(hi + rowoff224(n) + (uint32_t)k * 2) = __float2half_rn(v);
    }
}

// weights fp32 [N][K] -> XOR-swizzled fp16, RS-byte rows
template <int N, int K, int RS>
__device__ __forceinline__ void load_w_sw(const float* __restrict__ Wg,
                                          char* dst, int tid)
{
    for (int idx = tid; idx < N * K; idx += THREADS) {
        int n = idx / K, k = idx - n * K;
        uint32_t o = (uint32_t)(n * RS) + (((uint32_t)(k >> 3) ^ (uint32_t)(n & 7)) << 4)
                   + (uint32_t)(k & 7) * 2;
        *(__half*)(dst + o) = __float2half_rn(__ldg(&Wg[idx]));
    }
}

// cp.async one pre-converted X tile; NTHR participating threads (t0-based)
template <int NTHR>
__device__ __forceinline__ void stage_cp(const char* __restrict__ g, uint32_t sdst, int t0)
{
#pragma unroll
    for (int i = 0; i < (XTILE_BYTES / 16 + NTHR - 1) / NTHR; i++) {
        int off = (t0 + i * NTHR) * 16;
        if (off < XTILE_BYTES)
            asm volatile("cp.async.cg.shared.global [%0], [%1], 16;"
                         :: "r"(sdst + (uint32_t)off), "l"(g + off) : "memory");
    }
    asm volatile("cp.async.commit_group;" ::: "memory");
}

// ---------------- prepass: res fp32 -> fp16 grouped-224 tiles (pad-only zero) ----------------
__global__ void prep_x(const float* __restrict__ res, int ntiles)
{
    const int tt = blockIdx.x;
    const int tid = threadIdx.x;
    if (tt == 0 && tid < 6) g_work[tid] = 0;    // reset work-steal counters
    if (tt >= ntiles) return;
    char* dst = g_xf16 + (size_t)tt * XTILE_BYTES;
    const float4* src = (const float4*)(res + (size_t)tt * 6400);
    for (int gi = tid; gi < 1600; gi += 256) {
        int r = gi / 25, j = gi - r * 25;
        float4 v = __ldg(src + gi);
        __half2 h0 = __floats2half2_rn(v.x, v.y);
        __half2 h1 = __floats2half2_rn(v.z, v.w);
        *(uint2*)(dst + rowoff224(r) + (uint32_t)j * 8) =
            make_uint2(*(uint32_t*)&h0, *(uint32_t*)&h1);
    }
    for (int i = tid; i < 64 * 3; i += 256) {   // zero only pad bytes [200,224) per row
        int r = i / 3, j = i - r * 3;
        *(uint64_t*)(dst + rowoff224(r) + 200 + (uint32_t)j * 8) = 0ull;
    }
}

__global__ void __launch_bounds__(THREADS, 2) mlp_fused(
    const float* __restrict__ W1, const float* __restrict__ b1,
    const float* __restrict__ W2, const float* __restrict__ b2,
    const float* __restrict__ W3, const float* __restrict__ b3,
    const float* __restrict__ W4, const float* __restrict__ b4,
    const float* __restrict__ coupling,
    float* __restrict__ act_out, float* __restrict__ raw_out)
{
    extern __shared__ char smem[];
    const uint32_t sb = smem_u32(smem);
    const int tid = threadIdx.x, lane = tid & 31, wid = tid >> 5;
    const int half = wid >> 3, hwid = wid & 7, htid = tid & 255;
    const int barid = half + 1;
    const int c = blockIdx.x % 6;

    const uint32_t hbs = sb + half * ACT_STRIDE;
    uint32_t* b1h = (uint32_t*)(smem + B1H);
    uint32_t* b2h = (uint32_t*)(smem + B2H);
    float* b3s  = (float*)(smem + B3S);
    float* w4s  = (float*)(smem + W4S);
    float* b4s  = (float*)(smem + B4S);
    int*   wrk  = (int*)(smem + WRK);    // [0]=flag [1]=cur [2]=nxt

    // ---- steal first two groups; weights + biases (ONCE per CTA lifetime) ----
    if (tid == 0) {
        wrk[1] = atomicAdd(&g_work[c], 1);
        wrk[2] = atomicAdd(&g_work[c], 1);
    }
    load_w1(W1 + (size_t)c * 128 * 100, smem + W1_HI, tid);
    load_w_sw<64, 128, 256>(W2 + (size_t)c * 64 * 128, smem + W2_OFF, tid);
    load_w_sw<32, 64, 128>(W3 + (size_t)c * 32 * 64, smem + W3_OFF, tid);
    if (tid < 64) {
        __half2 h = __floats2half2_rn(__ldg(&b1[c * 128 + 2 * tid]),
                                      __ldg(&b1[c * 128 + 2 * tid + 1]));
        b1h[tid] = *(uint32_t*)&h;
    }
    if (tid < 32) {
        __half2 h = __floats2half2_rn(__ldg(&b2[c * 64 + 2 * tid]),
                                      __ldg(&b2[c * 64 + 2 * tid + 1]));
        b2h[tid] = *(uint32_t*)&h;
        b3s[tid] = __ldg(&b3[c * 32 + tid]);
        w4s[tid] = __ldg(&W4[c * 32 + tid]);
    }
    if (tid == 0) b4s[0] = __ldg(&b4[c]);
    __syncthreads();

    int cur = wrk[1], nxt = wrk[2];   // 48 CTAs x 2 grabs = 96 < 256: cur always valid

    stage_cp<256>(g_xf16 + (size_t)(cur * 16 + half) * XTILE_BYTES, hbs + XH1_OFF, htid);
    CP_WAIT();
    __syncthreads();

    const int g = lane >> 3, rl = lane & 7;
    const uint32_t sA = (uint32_t)rl;
    const uint32_t acp = (uint32_t)(g >> 1);
    const uint32_t bcp = (uint32_t)(g & 1);

    // layer-1 lane-resolved offsets (mainloop + k8 tail)
    const int l1_rb = (hwid >> 2) * 32, l1_nb = (hwid & 3) * 32;
    const uint32_t a1main = rowoff224(l1_rb + (g & 1) * 8 + rl) + (g >> 1) * 16;
    const uint32_t b1main = rowoff224(l1_nb + (g >> 1) * 8 + rl) + (g & 1) * 16;
    const uint32_t a1tail = rowoff224(l1_rb + (lane & 15) + ((lane >> 4) << 4)) + 192;
    const uint32_t b1tail = rowoff224(l1_nb + lane) + 192;

    while (true) {
        for (int t = 0; t < GTILES; t++) {
            const int row0 = cur * 1024 + t * 128 + half * 64;

            // ---- layer 1: X[64x100] @ W1[128x100]^T (6xk16 + 1xk8) ----
            float acc1[2][4][4];
#pragma unroll
            for (int mt = 0; mt < 2; mt++)
#pragma unroll
                for (int nt = 0; nt < 4; nt++)
#pragma unroll
                    for (int i = 0; i < 4; i++) acc1[mt][nt][i] = 0.0f;
            mma_loop_lin<2, 2, 6>(acc1,
                hbs + XH1_OFF + a1main, 3616,
                sb + W1_HI + b1main, 3616);
            {   // k8 tail: cols 96..103 (100..103 zero)
                uint32_t aa[4], bb[4];
                LDSM4(aa[0], aa[1], aa[2], aa[3], hbs + XH1_OFF + a1tail);
                LDSM4(bb[0], bb[1], bb[2], bb[3], sb + W1_HI + b1tail);
#pragma unroll
                for (int nt = 0; nt < 4; nt++) {
                    mma16808(acc1[0][nt], aa[0], aa[1], bb[nt]);
                    mma16808(acc1[1][nt], aa[2], aa[3], bb[nt]);
                }
            }
            BARH(barid);   // X reads done -> region0 reusable for H1

            epi_store_h2<2, 4, 256>(acc1, b1h, hbs + XH1_OFF, l1_rb, l1_nb, lane);
            BARH(barid);   // H1 ready

            // ---- layer 2: H1[64x128] @ W2[64x128]^T -> H2[64x64] ----
            {
                float acc[1][4][4];
                const int ar = (hwid >> 1) * 16 + (g & 1) * 8 + rl;
                const int br = (hwid & 1) * 32 + (g >> 1) * 8 + rl;
                mma_loop_sw<1, 2, 8>(acc,
                    hbs + XH1_OFF + (uint32_t)ar * 256, sA, acp, 0,
                    sb + W2_OFF + (uint32_t)br * 256, sA, bcp, 4096);
                epi_store_h2<1, 4, 128>(acc, b2h, hbs + H2_OFF,
                                        (hwid >> 1) * 16, (hwid & 1) * 32, lane);
            }
            BARH(barid);   // H2 ready; H1 reads done -> region0 free

            // ---- layer 3+4 (warps 0-3) || next-X prefetch (warps 4-7) ----
            if (hwid < 4) {
                float acc[1][4][4];
                const int rbase = hwid * 16;
                const int ar = rbase + (g & 1) * 8 + rl;
                const int br = (g >> 1) * 8 + rl;
                mma_loop_sw<1, 2, 4>(acc,
                    hbs + H2_OFF + (uint32_t)ar * 128, sA, acp, 0,
                    sb + W3_OFF + (uint32_t)br * 128, sA, bcp, 2048);
                const int qr = lane >> 2, qk = (lane & 3) * 2;
                float p0 = 0.0f, p1 = 0.0f;
#pragma unroll
                for (int nt = 0; nt < 4; nt++) {
                    const int col = nt * 8 + qk;
                    const float w0 = w4s[col], w1 = w4s[col + 1];
                    const float c0 = b3s[col], c1 = b3s[col + 1];
                    p0 += silu_f(acc[0][nt][0] + c0) * w0 + silu_f(acc[0][nt][1] + c1) * w1;
                    p1 += silu_f(acc[0][nt][2] + c0) * w0 + silu_f(acc[0][nt][3] + c1) * w1;
                }
                p0 += __shfl_xor_sync(0xFFFFFFFFu, p0, 1);
                p0 += __shfl_xor_sync(0xFFFFFFFFu, p0, 2);
                p1 += __shfl_xor_sync(0xFFFFFFFFu, p1, 1);
                p1 += __shfl_xor_sync(0xFFFFFFFFu, p1, 2);
                if ((lane & 3) == 0) {
                    const float bb = b4s[0];
                    raw_out[(size_t)(row0 + rbase + qr) * 6 + c]     = p0 + bb;
                    raw_out[(size_t)(row0 + rbase + qr + 8) * 6 + c] = p1 + bb;
                }
            } else {
                if (t + 1 < GTILES)
                    stage_cp<128>(g_xf16 + (size_t)(cur * 16 + (t + 1) * 2 + half) * XTILE_BYTES,
                                  hbs + XH1_OFF, htid - 128);
                else if (nxt < GROUPS)
                    stage_cp<128>(g_xf16 + (size_t)(nxt * 16 + half) * XTILE_BYTES,
                                  hbs + XH1_OFF, htid - 128);
                CP_WAIT();
            }
            BARH(barid);   // next X ready
        }

        // ---- group end: handshake, steal next group, maybe run coupling ----
        __threadfence();
        __syncthreads();
        if (tid == 0) {
            wrk[0] = atomicAdd(&g_cnt[cur], 1);
            wrk[1] = nxt;
            wrk[2] = (nxt < GROUPS) ? atomicAdd(&g_work[c], 1) : (1 << 20);
        }
        __syncthreads();
        const int f = wrk[0];
        const int ogrp = cur;
        cur = wrk[1];
        nxt = wrk[2];

        if (f == 5) {                 // 6th (last) chamber-CTA for ogrp
            if (tid == 0) g_cnt[ogrp] = 0;
            const float decay[6] = {0.9f, 0.93f, 0.85f, 0.97f, 0.88f, 0.94f};
#pragma unroll
            for (int rr = 0; rr < 2; rr++) {
                const int row = ogrp * 1024 + rr * 512 + tid;
                float a[6];
#pragma unroll
                for (int i = 0; i < 6; i++) {
                    float r = raw_out[(size_t)row * 6 + i];
                    a[i] = __fdividef(1.0f, 1.0f + __expf(-r));
                }
#pragma unroll
                for (int it = 0; it < 5; it++) {
#pragma unroll
                    for (int i = 0; i < 6; i++) a[i] *= decay[i];
                    float na[6];
#pragma unroll
                    for (int i = 0; i < 6; i++) {
                        float s = 0.0f;
#pragma unroll
                        for (int j = 0; j < 6; j++)
                            s += __ldg(&coupling[i * 6 + j]) * __sinf(a[j] - a[i]);
                        na[i] = a[i] + 0.02f * s;
                    }
#pragma unroll
                    for (int i = 0; i < 6; i++) a[i] = fminf(fmaxf(na[i], 0.0f), 1.0f);
                }
#pragma unroll
                for (int i = 0; i < 6; i++) act_out[(size_t)row * 6 + i] = a[i];
            }
        }

        if (cur >= GROUPS) break;
    }
}

extern "C" void kernel_launch(void* const* d_in, const int* in_sizes, int n_in,
                              void* d_out, int out_size)
{
    const float* res      = (const float*)d_in[0];
    const float* W1       = (const float*)d_in[1];
    const float* b1       = (const float*)d_in[2];
    const float* W2       = (const float*)d_in[3];
    const float* b2       = (const float*)d_in[4];
    const float* W3       = (const float*)d_in[5];
    const float* b3       = (const float*)d_in[6];
    const float* W4       = (const float*)d_in[7];
    const float* b4       = (const float*)d_in[8];
    const float* coupling = (const float*)d_in[9];

    int Btot = in_sizes[0] / 100;
    float* act = (float*)d_out;
    float* raw = act + (size_t)Btot * 6;
    int ntiles = Btot / 64;

    prep_x<<<ntiles, 256>>>(res, ntiles);
    cudaFuncSetAttribute(mlp_fused, cudaFuncAttributeMaxDynamicSharedMemorySize, SMEM_BYTES);
    mlp_fused<<<NBLOCKS, THREADS, SMEM_BYTES>>>(W1, b1, W2, b2, W3, b3, W4, b4,
                                                coupling, act, raw);
}

// round 17
// speedup vs baseline: 1.1445x; 1.0349x over previous
#include <cuda_runtime.h>
#include <cuda_fp16.h>
#include <cstdint>

#define THREADS 512
#define GTILES  2                   // tiles (128 rows) per work group
#define GROUPS  1024                // row-groups of 256 rows
#define NBLOCKS 288                 // persistent: 6 chambers x 48 CTAs (single wave)
#define XTILE_BYTES 14464           // one 64-row fp16 X tile, grouped-224 layout

// ---------------- smem layout (bytes), per CTA (2 CTAs/SM) ----------------
#define ACT_STRIDE 24576    // per-half activation block (region0 + H2)
#define XH1_OFF 0           // 16384 (X grouped-224 aliased with H1 64x256B swz)
#define H2_OFF  16384       // 8192  (64 x 128B swz)
#define W1_HI   49152       // 28928 (128 rows grouped-224)
#define W2_OFF  78080       // 16384 (64 x 256B swz)
#define W3_OFF  94464       // 4096  (32 x 128B swz)
#define B1H     98560       // half2 [64]  (256B)
#define B2H     98816       // half2 [32]  (128B)
#define B3S     98944       // fp32 [32]
#define W4S     99072       // fp32 [32]
#define B4S     99200       // fp32 [1]
#define WRK     99204       // int [3]: flag, cur, nxt
#define SMEM_BYTES 99328    // x2 = 198656 <= SM smem

__device__ int g_cnt[GROUPS];   // per-group completion counters (self-resetting)
__device__ int g_work[6];       // per-chamber group-steal counters (zeroed by prep_x)
__device__ __align__(16) char g_xf16[4096 * XTILE_BYTES];   // prepass fp16 X tiles

__device__ __forceinline__ uint32_t smem_u32(const void* p) {
    uint32_t a;
    asm("{ .reg .u64 t; cvta.to.shared.u64 t, %1; cvt.u32.u64 %0, t; }"
        : "=r"(a) : "l"(p));
    return a;
}

__host__ __device__ __forceinline__ uint32_t rowoff224(int r) {
    return (uint32_t)((r >> 3) * 1808 + (r & 7) * 224 + ((r & 4) << 2));
}

#define LDSM4(R0, R1, R2, R3, ADDR)                                        \
    asm volatile("ldmatrix.sync.aligned.m8n8.x4.shared.b16 {%0,%1,%2,%3},[%4];" \
                 : "=r"(R0), "=r"(R1), "=r"(R2), "=r"(R3) : "r"(ADDR))

#define STS32(ADDR, V) \
    asm volatile("st.shared.b32 [%0], %1;" :: "r"(ADDR), "r"(V) : "memory")

#define BARH(id) asm volatile("bar.sync %0, 256;" :: "r"(id) : "memory")
#define CP_WAIT() asm volatile("cp.async.wait_group 0;" ::: "memory")

__device__ __forceinline__ void mma16816(float c[4], const uint32_t a[4],
                                         uint32_t b0, uint32_t b1) {
    asm volatile(
        "mma.sync.aligned.m16n8k16.row.col.f32.f16.f16.f32 "
        "{%0,%1,%2,%3},{%4,%5,%6,%7},{%8,%9},{%0,%1,%2,%3};\n"
        : "+f"(c[0]), "+f"(c[1]), "+f"(c[2]), "+f"(c[3])
        : "r"(a[0]), "r"(a[1]), "r"(a[2]), "r"(a[3]), "r"(b0), "r"(b1));
}

__device__ __forceinline__ void mma16808(float c[4], uint32_t a0, uint32_t a1,
                                         uint32_t b0) {
    asm volatile(
        "mma.sync.aligned.m16n8k8.row.col.f32.f16.f16.f32 "
        "{%0,%1,%2,%3},{%4,%5},{%6},{%0,%1,%2,%3};\n"
        : "+f"(c[0]), "+f"(c[1]), "+f"(c[2]), "+f"(c[3])
        : "r"(a0), "r"(a1), "r"(b0));
}

__device__ __forceinline__ float silu_f(float x) {
    float t;
    asm("tanh.approx.f32 %0, %1;" : "=f"(t) : "f"(0.5f * x));
    return x * fmaf(0.5f, t, 0.5f);
}

__device__ __forceinline__ __half2 silu_h2(__half2 x) {
    const __half2 h05 = __floats2half2_rn(0.5f, 0.5f);
    __half2 t = __hmul2(x, h05);
    uint32_t th;
    asm("tanh.approx.f16x2 %0, %1;" : "=r"(th) : "r"(*(uint32_t*)&t));
    __half2 s = __hfma2(*(__half2*)&th, h05, h05);
    return __hmul2(x, s);
}

// ---------------- linear mainloop (layer 1: grouped-224 A and B) ----------------
template <int MT, int NTP, int KT>
__device__ __forceinline__ void mma_loop_lin(float acc[MT][NTP * 2][4],
    uint32_t aaddr, uint32_t amt, uint32_t baddr, uint32_t bnp)
{
#pragma unroll
    for (int kt = 0; kt < KT; kt++) {
        uint32_t ah[MT][4], bh[NTP][4];
#pragma unroll
        for (int mt = 0; mt < MT; mt++)
            LDSM4(ah[mt][0], ah[mt][1], ah[mt][2], ah[mt][3], aaddr + mt * amt + kt * 32);
#pragma unroll
        for (int np = 0; np < NTP; np++)
            LDSM4(bh[np][0], bh[np][1], bh[np][2], bh[np][3], baddr + np * bnp + kt * 32);
#pragma unroll
        for (int np = 0; np < NTP; np++)
#pragma unroll
            for (int mt = 0; mt < MT; mt++) {
                mma16816(acc[mt][2 * np],     ah[mt], bh[np][0], bh[np][1]);
                mma16816(acc[mt][2 * np + 1], ah[mt], bh[np][2], bh[np][3]);
            }
    }
}

// ---------------- swizzled mainloop (layers 2/3: XOR chunk^=(row&7)) ----------------
template <int MT, int NTP, int KT>
__device__ __forceinline__ void mma_loop_sw(float acc[MT][NTP * 2][4],
    uint32_t arow, uint32_t as, uint32_t acp, uint32_t amt,
    uint32_t brow, uint32_t bs, uint32_t bcp, uint32_t bnp)
{
#pragma unroll
    for (int mt = 0; mt < MT; mt++)
#pragma unroll
        for (int nt = 0; nt < NTP * 2; nt++)
#pragma unroll
            for (int i = 0; i < 4; i++) acc[mt][nt][i] = 0.0f;

#pragma unroll
    for (int kt = 0; kt < KT; kt++) {
        uint32_t ah[MT][4], bh[NTP][4];
        const uint32_t ac = (((uint32_t)(kt * 2) + acp) ^ as) << 4;
        const uint32_t bc = (((uint32_t)(kt * 2) + bcp) ^ bs) << 4;
#pragma unroll
        for (int mt = 0; mt < MT; mt++)
            LDSM4(ah[mt][0], ah[mt][1], ah[mt][2], ah[mt][3], arow + mt * amt + ac);
#pragma unroll
        for (int np = 0; np < NTP; np++)
            LDSM4(bh[np][0], bh[np][1], bh[np][2], bh[np][3], brow + np * bnp + bc);
#pragma unroll
        for (int np = 0; np < NTP; np++)
#pragma unroll
            for (int mt = 0; mt < MT; mt++) {
                mma16816(acc[mt][2 * np],     ah[mt], bh[np][0], bh[np][1]);
                mma16816(acc[mt][2 * np + 1], ah[mt], bh[np][2], bh[np][3]);
            }
    }
}

// epilogue: packed half2 bias + silu -> fp16 XOR-swizzled dest (RS-byte rows)
template <int MT, int NT, int RS>
__device__ __forceinline__ void epi_store_h2(float acc[MT][NT][4],
    const uint32_t* __restrict__ biash, uint32_t hbase, int rbase, int nbase, int lane)
{
    const int qr = lane >> 2, qk = (lane & 3) * 2;
#pragma unroll
    for (int mt = 0; mt < MT; mt++) {
        const int r0 = rbase + mt * 16 + qr;
        const int r1 = r0 + 8;
#pragma unroll
        for (int nt = 0; nt < NT; nt++) {
            const int col = nbase + nt * 8 + qk;
            const uint32_t ch = (uint32_t)(col >> 3);
            const uint32_t bb = biash[col >> 1];
            __half2 x0 = __hadd2(__floats2half2_rn(acc[mt][nt][0], acc[mt][nt][1]),
                                 *(const __half2*)&bb);
            __half2 x1 = __hadd2(__floats2half2_rn(acc[mt][nt][2], acc[mt][nt][3]),
                                 *(const __half2*)&bb);
            __half2 o0 = silu_h2(x0);
            __half2 o1 = silu_h2(x1);
            const uint32_t off0 = (uint32_t)(r0 * RS) + ((ch ^ (uint32_t)(r0 & 7)) << 4) + qk * 2;
            const uint32_t off1 = (uint32_t)(r1 * RS) + ((ch ^ (uint32_t)(r1 & 7)) << 4) + qk * 2;
            STS32(hbase + off0, *(uint32_t*)&o0);
            STS32(hbase + off1, *(uint32_t*)&o1);
        }
    }
}

// W1 fp32 [128][100] -> grouped-224 fp16; zero pad k in [100,112)
__device__ __forceinline__ void load_w1(const float* __restrict__ Wg,
                                        char* hi, int tid)
{
    for (int idx = tid; idx < 128 * 112; idx += THREADS) {
        int n = idx / 112, k = idx - n * 112;
        float v = (k < 100) ? __ldg(&Wg[n * 100 + k]) : 0.0f;
        *(__half*)(hi + rowoff224(n) + (uint32_t)k * 2) = __float2half_rn(v);
    }
}

// weights fp32 [N][K] -> XOR-swizzled fp16, RS-byte rows
template <int N, int K, int RS>
__device__ __forceinline__ void load_w_sw(const float* __restrict__ Wg,
                                          char* dst, int tid)
{
    for (int idx = tid; idx < N * K; idx += THREADS) {
        int n = idx / K, k = idx - n * K;
        uint32_t o = (uint32_t)(n * RS) + (((uint32_t)(k >> 3) ^ (uint32_t)(n & 7)) << 4)
                   + (uint32_t)(k & 7) * 2;
        *(__half*)(dst + o) = __float2half_rn(__ldg(&Wg[idx]));
    }
}

// cp.async one pre-converted X tile; NTHR participating threads (t0-based)
template <int NTHR>
__device__ __forceinline__ void stage_cp(const char* __restrict__ g, uint32_t sdst, int t0)
{
#pragma unroll
    for (int i = 0; i < (XTILE_BYTES / 16 + NTHR - 1) / NTHR; i++) {
        int off = (t0 + i * NTHR) * 16;
        if (off < XTILE_BYTES)
            asm volatile("cp.async.cg.shared.global [%0], [%1], 16;"
                         :: "r"(sdst + (uint32_t)off), "l"(g + off) : "memory");
    }
    asm volatile("cp.async.commit_group;" ::: "memory");
}

// ---------------- prepass: res fp32 -> fp16 grouped-224 tiles (pad-only zero) ----------------
__global__ void prep_x(const float* __restrict__ res, int ntiles)
{
    const int tt = blockIdx.x;
    const int tid = threadIdx.x;
    if (tt == 0 && tid < 6) g_work[tid] = 0;    // reset work-steal counters
    if (tt >= ntiles) return;
    char* dst = g_xf16 + (size_t)tt * XTILE_BYTES;
    const float4* src = (const float4*)(res + (size_t)tt * 6400);
    for (int gi = tid; gi < 1600; gi += 256) {
        int r = gi / 25, j = gi - r * 25;
        float4 v = __ldg(src + gi);
        __half2 h0 = __floats2half2_rn(v.x, v.y);
        __half2 h1 = __floats2half2_rn(v.z, v.w);
        *(uint2*)(dst + rowoff224(r) + (uint32_t)j * 8) =
            make_uint2(*(uint32_t*)&h0, *(uint32_t*)&h1);
    }
    for (int i = tid; i < 64 * 3; i += 256) {   // zero only pad bytes [200,224) per row
        int r = i / 3, j = i - r * 3;
        *(uint64_t*)(dst + rowoff224(r) + 200 + (uint32_t)j * 8) = 0ull;
    }
}

__global__ void __launch_bounds__(THREADS, 2) mlp_fused(
    const float* __restrict__ W1, const float* __restrict__ b1,
    const float* __restrict__ W2, const float* __restrict__ b2,
    const float* __restrict__ W3, const float* __restrict__ b3,
    const float* __restrict__ W4, const float* __restrict__ b4,
    const float* __restrict__ coupling,
    float* __restrict__ act_out, float* __restrict__ raw_out)
{
    extern __shared__ char smem[];
    const uint32_t sb = smem_u32(smem);
    const int tid = threadIdx.x, lane = tid & 31, wid = tid >> 5;
    const int half = wid >> 3, hwid = wid & 7, htid = tid & 255;
    const int barid = half + 1;
    const int c = blockIdx.x % 6;

    const uint32_t hbs = sb + half * ACT_STRIDE;
    uint32_t* b1h = (uint32_t*)(smem + B1H);
    uint32_t* b2h = (uint32_t*)(smem + B2H);
    float* b3s  = (float*)(smem + B3S);
    float* w4s  = (float*)(smem + W4S);
    float* b4s  = (float*)(smem + B4S);
    int*   wrk  = (int*)(smem + WRK);    // [0]=flag [1]=cur [2]=nxt

    // ---- steal first two groups; weights + biases (ONCE per CTA lifetime) ----
    if (tid == 0) {
        wrk[1] = atomicAdd(&g_work[c], 1);
        wrk[2] = atomicAdd(&g_work[c], 1);
    }
    load_w1(W1 + (size_t)c * 128 * 100, smem + W1_HI, tid);
    load_w_sw<64, 128, 256>(W2 + (size_t)c * 64 * 128, smem + W2_OFF, tid);
    load_w_sw<32, 64, 128>(W3 + (size_t)c * 32 * 64, smem + W3_OFF, tid);
    if (tid < 64) {
        __half2 h = __floats2half2_rn(__ldg(&b1[c * 128 + 2 * tid]),
                                      __ldg(&b1[c * 128 + 2 * tid + 1]));
        b1h[tid] = *(uint32_t*)&h;
    }
    if (tid < 32) {
        __half2 h = __floats2half2_rn(__ldg(&b2[c * 64 + 2 * tid]),
                                      __ldg(&b2[c * 64 + 2 * tid + 1]));
        b2h[tid] = *(uint32_t*)&h;
        b3s[tid] = __ldg(&b3[c * 32 + tid]);
        w4s[tid] = __ldg(&W4[c * 32 + tid]);
    }
    if (tid == 0) b4s[0] = __ldg(&b4[c]);
    __syncthreads();

    int cur = wrk[1], nxt = wrk[2];   // 48 CTAs x 2 grabs = 96 < 1024: cur valid

    stage_cp<256>(g_xf16 + (size_t)(cur * 4 + half) * XTILE_BYTES, hbs + XH1_OFF, htid);
    CP_WAIT();
    __syncthreads();

    const int g = lane >> 3, rl = lane & 7;
    const uint32_t sA = (uint32_t)rl;
    const uint32_t acp = (uint32_t)(g >> 1);
    const uint32_t bcp = (uint32_t)(g & 1);

    // layer-1 lane-resolved offsets (mainloop + k8 tail)
    const int l1_rb = (hwid >> 2) * 32, l1_nb = (hwid & 3) * 32;
    const uint32_t a1main = rowoff224(l1_rb + (g & 1) * 8 + rl) + (g >> 1) * 16;
    const uint32_t b1main = rowoff224(l1_nb + (g >> 1) * 8 + rl) + (g & 1) * 16;
    const uint32_t a1tail = rowoff224(l1_rb + (lane & 15) + ((lane >> 4) << 4)) + 192;
    const uint32_t b1tail = rowoff224(l1_nb + lane) + 192;

    while (true) {
        for (int t = 0; t < GTILES; t++) {
            const int row0 = cur * 256 + t * 128 + half * 64;

            // ---- layer 1: X[64x100] @ W1[128x100]^T (6xk16 + 1xk8) ----
            float acc1[2][4][4];
#pragma unroll
            for (int mt = 0; mt < 2; mt++)
#pragma unroll
                for (int nt = 0; nt < 4; nt++)
#pragma unroll
                    for (int i = 0; i < 4; i++) acc1[mt][nt][i] = 0.0f;
            mma_loop_lin<2, 2, 6>(acc1,
                hbs + XH1_OFF + a1main, 3616,
                sb + W1_HI + b1main, 3616);
            {   // k8 tail: cols 96..103 (100..103 zero)
                uint32_t aa[4], bb[4];
                LDSM4(aa[0], aa[1], aa[2], aa[3], hbs + XH1_OFF + a1tail);
                LDSM4(bb[0], bb[1], bb[2], bb[3], sb + W1_HI + b1tail);
#pragma unroll
                for (int nt = 0; nt < 4; nt++) {
                    mma16808(acc1[0][nt], aa[0], aa[1], bb[nt]);
                    mma16808(acc1[1][nt], aa[2], aa[3], bb[nt]);
                }
            }
            BARH(barid);   // X reads done -> region0 reusable for H1

            epi_store_h2<2, 4, 256>(acc1, b1h, hbs + XH1_OFF, l1_rb, l1_nb, lane);
            BARH(barid);   // H1 ready

            // ---- layer 2: H1[64x128] @ W2[64x128]^T -> H2[64x64] ----
            {
                float acc[1][4][4];
                const int ar = (hwid >> 1) * 16 + (g & 1) * 8 + rl;
                const int br = (hwid & 1) * 32 + (g >> 1) * 8 + rl;
                mma_loop_sw<1, 2, 8>(acc,
                    hbs + XH1_OFF + (uint32_t)ar * 256, sA, acp, 0,
                    sb + W2_OFF + (uint32_t)br * 256, sA, bcp, 4096);
                epi_store_h2<1, 4, 128>(acc, b2h, hbs + H2_OFF,
                                        (hwid >> 1) * 16, (hwid & 1) * 32, lane);
            }
            BARH(barid);   // H2 ready; H1 reads done -> region0 free

            // ---- layer 3+4 (warps 0-3) || next-X prefetch (warps 4-7) ----
            if (hwid < 4) {
                float acc[1][4][4];
                const int rbase = hwid * 16;
                const int ar = rbase + (g & 1) * 8 + rl;
                const int br = (g >> 1) * 8 + rl;
                mma_loop_sw<1, 2, 4>(acc,
                    hbs + H2_OFF + (uint32_t)ar * 128, sA, acp, 0,
                    sb + W3_OFF + (uint32_t)br * 128, sA, bcp, 2048);
                const int qr = lane >> 2, qk = (lane & 3) * 2;
                float p0 = 0.0f, p1 = 0.0f;
#pragma unroll
                for (int nt = 0; nt < 4; nt++) {
                    const int col = nt * 8 + qk;
                    const float w0 = w4s[col], w1 = w4s[col + 1];
                    const float c0 = b3s[col], c1 = b3s[col + 1];
                    p0 += silu_f(acc[0][nt][0] + c0) * w0 + silu_f(acc[0][nt][1] + c1) * w1;
                    p1 += silu_f(acc[0][nt][2] + c0) * w0 + silu_f(acc[0][nt][3] + c1) * w1;
                }
                p0 += __shfl_xor_sync(0xFFFFFFFFu, p0, 1);
                p0 += __shfl_xor_sync(0xFFFFFFFFu, p0, 2);
                p1 += __shfl_xor_sync(0xFFFFFFFFu, p1, 1);
                p1 += __shfl_xor_sync(0xFFFFFFFFu, p1, 2);
                if ((lane & 3) == 0) {
                    const float bb = b4s[0];
                    raw_out[(size_t)(row0 + rbase + qr) * 6 + c]     = p0 + bb;
                    raw_out[(size_t)(row0 + rbase + qr + 8) * 6 + c] = p1 + bb;
                }
            } else {
                if (t + 1 < GTILES)
                    stage_cp<128>(g_xf16 + (size_t)(cur * 4 + (t + 1) * 2 + half) * XTILE_BYTES,
                                  hbs + XH1_OFF, htid - 128);
                else if (nxt < GROUPS)
                    stage_cp<128>(g_xf16 + (size_t)(nxt * 4 + half) * XTILE_BYTES,
                                  hbs + XH1_OFF, htid - 128);
                CP_WAIT();
            }
            BARH(barid);   // next X ready
        }

        // ---- group end: handshake, steal next group, maybe run coupling ----
        __threadfence();
        __syncthreads();
        if (tid == 0) {
            wrk[0] = atomicAdd(&g_cnt[cur], 1);
            wrk[1] = nxt;
            wrk[2] = (nxt < GROUPS) ? atomicAdd(&g_work[c], 1) : (1 << 20);
        }
        __syncthreads();
        const int f = wrk[0];
        const int ogrp = cur;
        cur = wrk[1];
        nxt = wrk[2];

        if (f == 5) {                 // 6th (last) chamber-CTA for ogrp
            if (tid == 0) g_cnt[ogrp] = 0;
            if (tid < 256) {
                const float decay[6] = {0.9f, 0.93f, 0.85f, 0.97f, 0.88f, 0.94f};
                const int row = ogrp * 256 + tid;
                float a[6];
#pragma unroll
                for (int i = 0; i < 6; i++) {
                    float r = raw_out[(size_t)row * 6 + i];
                    a[i] = __fdividef(1.0f, 1.0f + __expf(-r));
                }
#pragma unroll
                for (int it = 0; it < 5; it++) {
#pragma unroll
                    for (int i = 0; i < 6; i++) a[i] *= decay[i];
                    float na[6];
#pragma unroll
                    for (int i = 0; i < 6; i++) {
                        float s = 0.0f;
#pragma unroll
                        for (int j = 0; j < 6; j++)
                            s += __ldg(&coupling[i * 6 + j]) * __sinf(a[j] - a[i]);
                        na[i] = a[i] + 0.02f * s;
                    }
#pragma unroll
                    for (int i = 0; i < 6; i++) a[i] = fminf(fmaxf(na[i], 0.0f), 1.0f);
                }
#pragma unroll
                for (int i = 0; i < 6; i++) act_out[(size_t)row * 6 + i] = a[i];
            }
        }

        if (cur >= GROUPS) break;
    }
}

extern "C" void kernel_launch(void* const* d_in, const int* in_sizes, int n_in,
                              void* d_out, int out_size)
{
    const float* res      = (const float*)d_in[0];
    const float* W1       = (const float*)d_in[1];
    const float* b1       = (const float*)d_in[2];
    const float* W2       = (const float*)d_in[3];
    const float* b2       = (const float*)d_in[4];
    const float* W3       = (const float*)d_in[5];
    const float* b3       = (const float*)d_in[6];
    const float* W4       = (const float*)d_in[7];
    const float* b4       = (const float*)d_in[8];
    const float* coupling = (const float*)d_in[9];

    int Btot = in_sizes[0] / 100;
    float* act = (float*)d_out;
    float* raw = act + (size_t)Btot * 6;
    int ntiles = Btot / 64;

    prep_x<<<ntiles, 256>>>(res, ntiles);
    cudaFuncSetAttribute(mlp_fused, cudaFuncAttributeMaxDynamicSharedMemorySize, SMEM_BYTES);
    mlp_fused<<<NBLOCKS, THREADS, SMEM_BYTES>>>(W1, b1, W2, b2, W3, b3, W4, b4,
                                                coupling, act, raw);
}